// round 4
// baseline (speedup 1.0000x reference)
#include <cuda_runtime.h>
#include <cstdint>

// CRF log-partition forward scan, linear-domain, latency-optimized.
// B=64 batches, one block (128 threads) per batch; thread j owns tag j.
// exp(transitions) column j in 64 packed f32x2 regs.
//   u_t[j] = (sum_i u_{t-1}[i] * expT[i][j]) * exp(e_t[j]) * rscale
// No exp/log/div on the per-step critical chain:
//  - exp(e_t) via depth-4 raw/exp prefetch pipeline
//  - renormalization every 8 steps: exact max computed by warp 0 only
//    (off-chain), published via shared, applied ONE STEP LATER folded into
//    pe; only thread 0 accumulates the log offset C.

static constexpr int Bb = 64;
static constexpr int Ll = 512;
static constexpr int Nn = 128;

__device__ __forceinline__ unsigned long long fma2(unsigned long long a,
                                                   unsigned long long b,
                                                   unsigned long long c) {
    unsigned long long d;
    asm("fma.rn.f32x2 %0, %1, %2, %3;" : "=l"(d) : "l"(a), "l"(b), "l"(c));
    return d;
}
__device__ __forceinline__ unsigned long long add2(unsigned long long a,
                                                   unsigned long long b) {
    unsigned long long d;
    asm("add.rn.f32x2 %0, %1, %2;" : "=l"(d) : "l"(a), "l"(b));
    return d;
}
__device__ __forceinline__ unsigned long long pack2(float lo, float hi) {
    unsigned long long d;
    asm("mov.b64 %0, {%1, %2};" : "=l"(d) : "f"(lo), "f"(hi));
    return d;
}
__device__ __forceinline__ float lo2(unsigned long long v) {
    return __uint_as_float((unsigned)(v & 0xffffffffull));
}
__device__ __forceinline__ float hi2(unsigned long long v) {
    return __uint_as_float((unsigned)(v >> 32));
}

__global__ __launch_bounds__(128, 1)
void crf_forward_kernel(const float* __restrict__ emissions,
                        const float* __restrict__ transitions,
                        const float* __restrict__ start_t,
                        const float* __restrict__ end_t,
                        const int*   __restrict__ lengths,
                        float*       __restrict__ out)
{
    const int b    = blockIdx.x;
    const int j    = threadIdx.x;
    const int lane = j & 31;
    const int wid  = j >> 5;

    __shared__ __align__(16) float pbuf[2][Nn];
    __shared__ float red[8];   // red[0] = renorm scale; red[4..7] final reduce

    const float* E = emissions + (size_t)b * Ll * Nn;

    // expT column j packed (expT[2m][j], expT[2m+1][j])
    unsigned long long regT[64];
#pragma unroll
    for (int mI = 0; mI < 64; ++mI) {
        float lo = __expf(transitions[(2 * mI + 0) * Nn + j]);
        float hi = __expf(transitions[(2 * mI + 1) * Nn + j]);
        regT[mI] = pack2(lo, hi);
    }

    const int len  = lengths[b];
    const int last = len - 1;            // update steps t = 1..last

    float u = __expf(start_t[j] + E[j]); // u_0 ; offset C = 0
    float C  = 0.0f;                     // only thread 0's C is used
    float lM = 0.0f;                     // thread 0's pending log offset
    const float pend = __expf(end_t[j]);

    const float TGT       = 2.98023224e-8f;  // 2^-25 renorm target
    const float LOG_ITGT  = 17.3286795f;     // 25*ln2

    // emission prefetch pipeline: pe for t,t+1 ; raw for t+2,t+3
    float pe0 = 1.0f, pe1 = 1.0f, r2 = 0.0f, r3 = 0.0f;
    if (last >= 1) {
        int i1 = 1, i2 = 2 > last ? last : 2;
        int i3 = 3 > last ? last : 3, i4 = 4 > last ? last : 4;
        pe0 = __expf(E[(size_t)i1 * Nn + j]);
        pe1 = __expf(E[(size_t)i2 * Nn + j]);
        r2  = E[(size_t)i3 * Nn + j];
        r3  = E[(size_t)i4 * Nn + j];
    }

    auto step = [&](int t, int buf) {
        pbuf[buf][j] = u;
        __syncthreads();

        // apply stale renorm scale (computed last step by warp 0) — off-chain
        float pe_eff = pe0;
        if ((t & 7) == 5) {
            float rs = red[0];
            pe_eff = pe0 * rs;
            if (j == 0) C += lM;
        }
        // compute renorm scale from u_{t-1} (warp 0 only, consumed next step)
        if (((t & 7) == 4) && wid == 0) {
            float m0 = pbuf[buf][lane];
            float m1 = pbuf[buf][lane + 32];
            float m2 = pbuf[buf][lane + 64];
            float m3 = pbuf[buf][lane + 96];
            float m  = fmaxf(fmaxf(m0, m1), fmaxf(m2, m3));
#pragma unroll
            for (int off = 16; off > 0; off >>= 1)
                m = fmaxf(m, __shfl_xor_sync(0xffffffffu, m, off));
            if (lane == 0) {
                red[0] = __fdividef(TGT, m);
                lM = __logf(m) + LOG_ITGT;
            }
        }

        // s[j] = sum_i u_{t-1}[i] * expT[i][j]
        const ulonglong2* P = reinterpret_cast<const ulonglong2*>(pbuf[buf]);
        unsigned long long acc0 = 0ull, acc1 = 0ull, acc2 = 0ull, acc3 = 0ull;
#pragma unroll
        for (int k = 0; k < 32; k += 2) {
            ulonglong2 q = P[k];
            ulonglong2 r = P[k + 1];
            acc0 = fma2(q.x, regT[2 * k + 0], acc0);
            acc1 = fma2(q.y, regT[2 * k + 1], acc1);
            acc2 = fma2(r.x, regT[2 * k + 2], acc2);
            acc3 = fma2(r.y, regT[2 * k + 3], acc3);
        }
        acc0 = add2(acc0, acc1);
        acc2 = add2(acc2, acc3);
        acc0 = add2(acc0, acc2);
        u = (lo2(acc0) + hi2(acc0)) * pe_eff;

        // rotate prefetch pipeline (off-chain)
        float pe_new = __expf(r2);               // pe for t+2
        int tt = t + 4; tt = tt > last ? last : tt;
        float r_new = E[(size_t)tt * Nn + j];    // raw for t+4
        pe0 = pe1; pe1 = pe_new;
        r2  = r3;  r3  = r_new;
    };

    int t = 1;
    for (; t + 1 <= last; t += 2) {
        step(t, 1);
        step(t + 1, 0);
    }
    if (t <= last) step(t, 1);

    // out[b] = log( sum_j u[j] * exp(end[j]) ) + C
    float ex = u * pend;
#pragma unroll
    for (int off = 16; off > 0; off >>= 1)
        ex += __shfl_xor_sync(0xffffffffu, ex, off);
    if (lane == 0) red[4 + wid] = ex;
    __syncthreads();

    if (j == 0) {
        float ssum = red[4] + red[5] + red[6] + red[7];
        out[b] = __logf(ssum) + C;
    }
}

extern "C" void kernel_launch(void* const* d_in, const int* in_sizes, int n_in,
                              void* d_out, int out_size) {
    const float* emissions   = (const float*)d_in[0];
    const float* transitions = (const float*)d_in[1];
    const float* start_t     = (const float*)d_in[2];
    const float* end_t       = (const float*)d_in[3];
    const int*   lengths     = (const int*)  d_in[4];
    crf_forward_kernel<<<Bb, Nn>>>(emissions, transitions, start_t, end_t,
                                   lengths, (float*)d_out);
}

// round 6
// speedup vs baseline: 1.0003x; 1.0003x over previous
#include <cuda_runtime.h>
#include <cuda_bf16.h>
#include <cstdint>

// CRF log-partition forward scan on tensor cores via mma.sync (HMMA, bf16).
// B=64 batches, one block (128 threads) per batch. Linear-domain recurrence
//   u_t = diag(exp(e_t)) * expT^T * u_{t-1},   alpha = log u + C.
// Matvec = mma.m16n8k16 row.col f32.bf16.bf16.f32, M=128 rows split 32/warp
// (2 m-tiles), K=128 (8 k-tiles), N=8 with only column 0 meaningful.
// A-fragments (expT^T) stationary in registers; u carried in shared memory
// as bf16 in B-fragment-permuted order (lanes 0-3 load via 4x LDS.128),
// double-buffered. D col 0 lives on lanes%4==0 ("writers"): they scale by
// pe*rs and store u_t. pe (exp of emissions) staged in shared f32 by a
// depth-4 prefetch pipeline; renorm every 8 steps from writers' running max,
// applied stale. One __syncthreads per step; everything else off-chain.

static constexpr int Bb = 64;
static constexpr int Ll = 512;
static constexpr int Nn = 128;

__device__ __forceinline__ uint32_t pkbf(float lo, float hi) {
    unsigned short l = __bfloat16_as_ushort(__float2bfloat16(lo));
    unsigned short h = __bfloat16_as_ushort(__float2bfloat16(hi));
    return (uint32_t)l | ((uint32_t)h << 16);
}

// b16 index of row r in the B-fragment-permuted u layout
__device__ __forceinline__ int permb(int r) {
    int kt = r >> 4, kr = r & 15;
    int half = kr >> 3, tsel = (kr & 7) >> 1, lohi = kr & 1;
    return tsel * 32 + kt * 4 + half * 2 + lohi;
}

__device__ __forceinline__ uint32_t smem_u32(const void* p) {
    uint32_t a;
    asm("{ .reg .u64 t; cvta.to.shared.u64 t, %1; cvt.u32.u64 %0, t; }"
        : "=r"(a) : "l"(p));
    return a;
}

__device__ __forceinline__ void mma_bf16(float& d0, float& d1, float& d2, float& d3,
                                         uint32_t a0, uint32_t a1, uint32_t a2,
                                         uint32_t a3, uint32_t b0, uint32_t b1) {
    asm volatile(
        "mma.sync.aligned.m16n8k16.row.col.f32.bf16.bf16.f32 "
        "{%0,%1,%2,%3}, {%4,%5,%6,%7}, {%8,%9}, {%0,%1,%2,%3};"
        : "+f"(d0), "+f"(d1), "+f"(d2), "+f"(d3)
        : "r"(a0), "r"(a1), "r"(a2), "r"(a3), "r"(b0), "r"(b1));
}

__global__ __launch_bounds__(128, 1)
void crf_forward_kernel(const float* __restrict__ emissions,
                        const float* __restrict__ transitions,
                        const float* __restrict__ start_t,
                        const float* __restrict__ end_t,
                        const int*   __restrict__ lengths,
                        float*       __restrict__ out)
{
    const int b    = blockIdx.x;
    const int j    = threadIdx.x;
    const int lane = j & 31;
    const int wid  = j >> 5;

    __shared__ __align__(16) __nv_bfloat16 ubuf[2][Nn];  // permuted, dbl-buf
    __shared__ float pebuf[4][Nn];                       // exp(emissions) f32
    __shared__ float red[8];  // [0..3] warp maxes, [4..7] final reduce

    const float* E = emissions + (size_t)b * Ll * Nn;

    // ---- stationary A fragments: A[m][k] = exp(transitions[k][m]) ----
    const int g  = lane >> 2;
    const int cq = (lane & 3) * 2;
    uint32_t A[2][8][4];
#pragma unroll
    for (int mt = 0; mt < 2; ++mt) {
        const int r0 = wid * 32 + mt * 16 + g;
#pragma unroll
        for (int kt = 0; kt < 8; ++kt) {
            const int c0 = kt * 16 + cq;
            float t00 = __expf(transitions[(c0 + 0) * Nn + r0]);
            float t01 = __expf(transitions[(c0 + 1) * Nn + r0]);
            float t10 = __expf(transitions[(c0 + 0) * Nn + r0 + 8]);
            float t11 = __expf(transitions[(c0 + 1) * Nn + r0 + 8]);
            float t02 = __expf(transitions[(c0 + 8) * Nn + r0]);
            float t03 = __expf(transitions[(c0 + 9) * Nn + r0]);
            float t12 = __expf(transitions[(c0 + 8) * Nn + r0 + 8]);
            float t13 = __expf(transitions[(c0 + 9) * Nn + r0 + 8]);
            A[mt][kt][0] = pkbf(t00, t01);
            A[mt][kt][1] = pkbf(t10, t11);
            A[mt][kt][2] = pkbf(t02, t03);
            A[mt][kt][3] = pkbf(t12, t13);
        }
    }

    const int len  = lengths[b];
    const int last = len - 1;

    // ---- init u0, emission pipeline ----
    {
        float u0 = __expf(start_t[j] + E[j]);
        ubuf[0][permb(j)] = __float2bfloat16(u0);
    }
    auto ci = [&](int t) { return t > last ? last : t; };
    pebuf[1][j] = __expf(E[(size_t)ci(1) * Nn + j]);
    pebuf[2][j] = __expf(E[(size_t)ci(2) * Nn + j]);
    float r2 = E[(size_t)ci(3) * Nn + j];
    float r3 = E[(size_t)ci(4) * Nn + j];

    const float pend = __expf(end_t[j]);
    float C = 0.0f;                        // thread 0 only
    const float TGT      = 2.98023224e-8f; // 2^-25 renorm target
    const float LOG_ITGT = 17.3286795f;    // 25*ln2

    // writer row/address precompute (lanes % 4 == 0)
    const bool writer = (lane & 3) == 0;
    int rw0 = wid * 32 + g, rw1 = rw0 + 8, rw2 = rw0 + 16, rw3 = rw0 + 24;
    int pw0 = permb(rw0), pw1 = permb(rw1), pw2 = permb(rw2), pw3 = permb(rw3);

    const uint32_t ub_addr = smem_u32(&ubuf[0][0]);
    uint32_t Bv[16] = {0, 0, 0, 0, 0, 0, 0, 0, 0, 0, 0, 0, 0, 0, 0, 0};

    float lm = 0.0f;  // writers' running max of u
    for (int t = 1; t <= last; ++t) {
        __syncthreads();

        // B fragments: lanes 0-3 load permuted u_{t-1} (4x LDS.128)
        if (lane < 4) {
            const uint32_t base = ub_addr + (uint32_t)(((t & 1) ^ 1) * 256)
                                + (uint32_t)(lane * 64);
            asm volatile("ld.shared.v4.u32 {%0,%1,%2,%3}, [%4];"
                         : "=r"(Bv[0]), "=r"(Bv[1]), "=r"(Bv[2]), "=r"(Bv[3])
                         : "r"(base));
            asm volatile("ld.shared.v4.u32 {%0,%1,%2,%3}, [%4];"
                         : "=r"(Bv[4]), "=r"(Bv[5]), "=r"(Bv[6]), "=r"(Bv[7])
                         : "r"(base + 16));
            asm volatile("ld.shared.v4.u32 {%0,%1,%2,%3}, [%4];"
                         : "=r"(Bv[8]), "=r"(Bv[9]), "=r"(Bv[10]), "=r"(Bv[11])
                         : "r"(base + 32));
            asm volatile("ld.shared.v4.u32 {%0,%1,%2,%3}, [%4];"
                         : "=r"(Bv[12]), "=r"(Bv[13]), "=r"(Bv[14]), "=r"(Bv[15])
                         : "r"(base + 48));
        }

        // renorm bookkeeping (off-chain)
        float rs = 1.0f;
        if ((t & 7) == 4) {           // publish max(u_{<=t-1}) per warp
            float m = lm;
#pragma unroll
            for (int off = 16; off > 0; off >>= 1)
                m = fmaxf(m, __shfl_xor_sync(0xffffffffu, m, off));
            if (lane == 0) red[wid] = m;
            lm = 0.0f;
        } else if ((t & 7) == 5) {    // apply stale scale
            float m4 = fmaxf(fmaxf(red[0], red[1]), fmaxf(red[2], red[3]));
            rs = __fdividef(TGT, m4);
            if (j == 0) C += __logf(m4) + LOG_ITGT;
        }

        // 16 HMMA, 4 independent accumulator chains per m-tile
        float acc[2][4][4];
#pragma unroll
        for (int mt = 0; mt < 2; ++mt)
#pragma unroll
            for (int c = 0; c < 4; ++c)
#pragma unroll
                for (int i = 0; i < 4; ++i) acc[mt][c][i] = 0.0f;
#pragma unroll
        for (int kt = 0; kt < 8; ++kt) {
            mma_bf16(acc[0][kt & 3][0], acc[0][kt & 3][1],
                     acc[0][kt & 3][2], acc[0][kt & 3][3],
                     A[0][kt][0], A[0][kt][1], A[0][kt][2], A[0][kt][3],
                     Bv[2 * kt], Bv[2 * kt + 1]);
            mma_bf16(acc[1][kt & 3][0], acc[1][kt & 3][1],
                     acc[1][kt & 3][2], acc[1][kt & 3][3],
                     A[1][kt][0], A[1][kt][1], A[1][kt][2], A[1][kt][3],
                     Bv[2 * kt], Bv[2 * kt + 1]);
        }

        // emission prefetch producer (off-chain, hidden under HMMA)
        pebuf[(t + 2) & 3][j] = __expf(r2);
        r2 = r3;
        int tt = t + 4; tt = tt > last ? last : tt;
        r3 = E[(size_t)tt * Nn + j];

        // writers: fold pe*rs, store u_t (bf16, permuted, other buffer)
        if (writer) {
            float f0 = pebuf[t & 3][rw0] * rs;
            float f1 = pebuf[t & 3][rw1] * rs;
            float f2 = pebuf[t & 3][rw2] * rs;
            float f3 = pebuf[t & 3][rw3] * rs;
            float d0 = (acc[0][0][0] + acc[0][1][0]) + (acc[0][2][0] + acc[0][3][0]);
            float d1 = (acc[0][0][2] + acc[0][1][2]) + (acc[0][2][2] + acc[0][3][2]);
            float d2 = (acc[1][0][0] + acc[1][1][0]) + (acc[1][2][0] + acc[1][3][0]);
            float d3 = (acc[1][0][2] + acc[1][1][2]) + (acc[1][2][2] + acc[1][3][2]);
            float u0n = d0 * f0, u1n = d1 * f1, u2n = d2 * f2, u3n = d3 * f3;
            const int wb = t & 1;
            ubuf[wb][pw0] = __float2bfloat16(u0n);
            ubuf[wb][pw1] = __float2bfloat16(u1n);
            ubuf[wb][pw2] = __float2bfloat16(u2n);
            ubuf[wb][pw3] = __float2bfloat16(u3n);
            lm = fmaxf(lm, fmaxf(fmaxf(u0n, u1n), fmaxf(u2n, u3n)));
        }
    }

    __syncthreads();

    // out[b] = log( sum_j u_last[j] * exp(end[j]) ) + C
    float u  = __bfloat162float(ubuf[last & 1][permb(j)]);
    float ex = u * pend;
#pragma unroll
    for (int off = 16; off > 0; off >>= 1)
        ex += __shfl_xor_sync(0xffffffffu, ex, off);
    if (lane == 0) red[4 + wid] = ex;
    __syncthreads();
    if (j == 0)
        out[b] = __logf(red[4] + red[5] + red[6] + red[7]) + C;
}

extern "C" void kernel_launch(void* const* d_in, const int* in_sizes, int n_in,
                              void* d_out, int out_size) {
    const float* emissions   = (const float*)d_in[0];
    const float* transitions = (const float*)d_in[1];
    const float* start_t     = (const float*)d_in[2];
    const float* end_t       = (const float*)d_in[3];
    const int*   lengths     = (const int*)  d_in[4];
    crf_forward_kernel<<<Bb, Nn>>>(emissions, transitions, start_t, end_t,
                                   lengths, (float*)d_out);
}

// round 7
// speedup vs baseline: 1.2336x; 1.2333x over previous
#include <cuda_runtime.h>
#include <cuda_bf16.h>
#include <cstdint>

// CRF log-partition forward scan on tensor cores (mma.sync m16n8k16 bf16).
// B=64 batches, one block (128 threads) per batch. Linear-domain recurrence
//   u_t = diag(exp(e_t)) * expT^T * u_{t-1},  alpha = log u + C.
// Per-step critical chain ONLY: bar -> LDS.128 x4 (lanes 0-3, permuted u) ->
// 16 HMMA (4 chains x 2) -> add tree -> d*pe -> cvt bf16 -> STS x4 -> bar.
// Everything else (emission LDG+exp prefetch depth 4 in WRITER REGISTERS,
// renorm sampling/publish, C accumulation) issues after the u-store.
// Renorm every 8 steps, applied stale, sampled max (lane0 rows/warp),
// target 2^-30; scale folded into pe registers off the d-chain.

static constexpr int Bb = 64;
static constexpr int Ll = 512;
static constexpr int Nn = 128;

__device__ __forceinline__ uint32_t pkbf(float lo, float hi) {
    unsigned short l = __bfloat16_as_ushort(__float2bfloat16(lo));
    unsigned short h = __bfloat16_as_ushort(__float2bfloat16(hi));
    return (uint32_t)l | ((uint32_t)h << 16);
}

// b16 index of row r in the B-fragment-permuted u layout
__device__ __forceinline__ int permb(int r) {
    int kt = r >> 4, kr = r & 15;
    int half = kr >> 3, tsel = (kr & 7) >> 1, lohi = kr & 1;
    return tsel * 32 + kt * 4 + half * 2 + lohi;
}

__device__ __forceinline__ uint32_t smem_u32(const void* p) {
    uint32_t a;
    asm("{ .reg .u64 t; cvta.to.shared.u64 t, %1; cvt.u32.u64 %0, t; }"
        : "=r"(a) : "l"(p));
    return a;
}

__device__ __forceinline__ void mma_bf16(float& d0, float& d1, float& d2, float& d3,
                                         uint32_t a0, uint32_t a1, uint32_t a2,
                                         uint32_t a3, uint32_t b0, uint32_t b1) {
    asm volatile(
        "mma.sync.aligned.m16n8k16.row.col.f32.bf16.bf16.f32 "
        "{%0,%1,%2,%3}, {%4,%5,%6,%7}, {%8,%9}, {%0,%1,%2,%3};"
        : "+f"(d0), "+f"(d1), "+f"(d2), "+f"(d3)
        : "r"(a0), "r"(a1), "r"(a2), "r"(a3), "r"(b0), "r"(b1));
}

__global__ __launch_bounds__(128, 1)
void crf_forward_kernel(const float* __restrict__ emissions,
                        const float* __restrict__ transitions,
                        const float* __restrict__ start_t,
                        const float* __restrict__ end_t,
                        const int*   __restrict__ lengths,
                        float*       __restrict__ out)
{
    const int b    = blockIdx.x;
    const int j    = threadIdx.x;
    const int lane = j & 31;
    const int wid  = j >> 5;

    __shared__ __align__(16) __nv_bfloat16 ubuf[2][Nn];  // permuted, dbl-buf
    __shared__ float red[8];   // [0..3] renorm samples, [4..7] final reduce

    const float* E = emissions + (size_t)b * Ll * Nn;

    // ---- stationary A fragments: A[m][k] = exp(transitions[k][m]) ----
    const int g  = lane >> 2;
    const int cq = (lane & 3) * 2;
    uint32_t A[2][8][4];
#pragma unroll
    for (int mt = 0; mt < 2; ++mt) {
        const int r0 = wid * 32 + mt * 16 + g;
#pragma unroll
        for (int kt = 0; kt < 8; ++kt) {
            const int c0 = kt * 16 + cq;
            float t00 = __expf(transitions[(c0 + 0) * Nn + r0]);
            float t01 = __expf(transitions[(c0 + 1) * Nn + r0]);
            float t10 = __expf(transitions[(c0 + 0) * Nn + r0 + 8]);
            float t11 = __expf(transitions[(c0 + 1) * Nn + r0 + 8]);
            float t02 = __expf(transitions[(c0 + 8) * Nn + r0]);
            float t03 = __expf(transitions[(c0 + 9) * Nn + r0]);
            float t12 = __expf(transitions[(c0 + 8) * Nn + r0 + 8]);
            float t13 = __expf(transitions[(c0 + 9) * Nn + r0 + 8]);
            A[mt][kt][0] = pkbf(t00, t01);
            A[mt][kt][1] = pkbf(t10, t11);
            A[mt][kt][2] = pkbf(t02, t03);
            A[mt][kt][3] = pkbf(t12, t13);
        }
    }

    const int len  = lengths[b];
    const int last = len - 1;

    // u0 into buffer 0 (permuted bf16)
    ubuf[0][permb(j)] = __float2bfloat16(__expf(start_t[j] + E[j]));

    // writer setup: lanes with lane%4==0 own D column 0 rows {g,g+8,g+16,g+24}
    const bool writer = (lane & 3) == 0;
    const int rw0 = wid * 32 + g;
    const int pw0 = permb(rw0), pw1 = permb(rw0 + 8),
              pw2 = permb(rw0 + 16), pw3 = permb(rw0 + 24);

    // per-lane emission prefetch pipeline (rows rw0+{0,8,16,24}; indices are
    // valid for every lane, only writers' values get used)
    const float* Ew = E + rw0;
    auto ldE = [&](int t, int off) {
        int tt = t > last ? last : t;
        return Ew[(size_t)tt * Nn + off];
    };
    float peA[4], peB[4], rC[4], rD[4];
#pragma unroll
    for (int c = 0; c < 4; ++c) {
        peA[c] = __expf(ldE(1, c * 8));
        peB[c] = __expf(ldE(2, c * 8));
        rC[c]  = ldE(3, c * 8);
        rD[c]  = ldE(4, c * 8);
    }

    const float pend = __expf(end_t[j]);
    float C  = 0.0f;                        // thread 0 only
    float lm = 0.0f;                        // lane0: running max of its u rows
    const float TGT      = 9.31322575e-10f; // 2^-30 renorm target
    const float LOG_ITGT = 20.7944154f;     // 30*ln2

    const uint32_t ub_addr = smem_u32(&ubuf[0][0]);
    uint32_t Bv[16] = {0,0,0,0,0,0,0,0,0,0,0,0,0,0,0,0};

    auto step = [&](int t, int rb, int wb) {
        __syncthreads();

        // ---- chain: load permuted u_{t-1} (lanes 0-3) ----
        if (lane < 4) {
            const uint32_t base = ub_addr + (uint32_t)(rb * 256 + lane * 64);
            asm volatile("ld.shared.v4.u32 {%0,%1,%2,%3}, [%4];"
                         : "=r"(Bv[0]), "=r"(Bv[1]), "=r"(Bv[2]), "=r"(Bv[3])
                         : "r"(base));
            asm volatile("ld.shared.v4.u32 {%0,%1,%2,%3}, [%4];"
                         : "=r"(Bv[4]), "=r"(Bv[5]), "=r"(Bv[6]), "=r"(Bv[7])
                         : "r"(base + 16));
            asm volatile("ld.shared.v4.u32 {%0,%1,%2,%3}, [%4];"
                         : "=r"(Bv[8]), "=r"(Bv[9]), "=r"(Bv[10]), "=r"(Bv[11])
                         : "r"(base + 32));
            asm volatile("ld.shared.v4.u32 {%0,%1,%2,%3}, [%4];"
                         : "=r"(Bv[12]), "=r"(Bv[13]), "=r"(Bv[14]), "=r"(Bv[15])
                         : "r"(base + 48));
        }

        // stale renorm: fold scale into pe regs (independent of HMMA results,
        // hides under LDS+HMMA latency; 1-of-8 steps)
        if ((t & 7) == 5) {
            float m4 = fmaxf(fmaxf(red[0], red[1]), fmaxf(red[2], red[3]));
            float rs = __fdividef(TGT, m4);
            peA[0] *= rs; peA[1] *= rs; peA[2] *= rs; peA[3] *= rs;
            if (j == 0) C += __logf(m4) + LOG_ITGT;
        }

        // ---- chain: 16 HMMA, 4 accumulator chains x 2 m-tiles ----
        float acc[2][4][4];
#pragma unroll
        for (int mt = 0; mt < 2; ++mt)
#pragma unroll
            for (int c = 0; c < 4; ++c)
#pragma unroll
                for (int i = 0; i < 4; ++i) acc[mt][c][i] = 0.0f;
#pragma unroll
        for (int kt = 0; kt < 8; ++kt) {
            mma_bf16(acc[0][kt & 3][0], acc[0][kt & 3][1],
                     acc[0][kt & 3][2], acc[0][kt & 3][3],
                     A[0][kt][0], A[0][kt][1], A[0][kt][2], A[0][kt][3],
                     Bv[2 * kt], Bv[2 * kt + 1]);
            mma_bf16(acc[1][kt & 3][0], acc[1][kt & 3][1],
                     acc[1][kt & 3][2], acc[1][kt & 3][3],
                     A[1][kt][0], A[1][kt][1], A[1][kt][2], A[1][kt][3],
                     Bv[2 * kt], Bv[2 * kt + 1]);
        }

        // ---- chain: epilogue (d * pe, cvt, store) ----
        float d0 = (acc[0][0][0] + acc[0][1][0]) + (acc[0][2][0] + acc[0][3][0]);
        float d1 = (acc[0][0][2] + acc[0][1][2]) + (acc[0][2][2] + acc[0][3][2]);
        float d2 = (acc[1][0][0] + acc[1][1][0]) + (acc[1][2][0] + acc[1][3][0]);
        float d3 = (acc[1][0][2] + acc[1][1][2]) + (acc[1][2][2] + acc[1][3][2]);
        float u0n = d0 * peA[0], u1n = d1 * peA[1];
        float u2n = d2 * peA[2], u3n = d3 * peA[3];
        if (writer) {
            ubuf[wb][pw0] = __float2bfloat16(u0n);
            ubuf[wb][pw1] = __float2bfloat16(u1n);
            ubuf[wb][pw2] = __float2bfloat16(u2n);
            ubuf[wb][pw3] = __float2bfloat16(u3n);
        }

        // ---- off-chain tail (after the u-store) ----
        lm = fmaxf(lm, fmaxf(fmaxf(u0n, u1n), fmaxf(u2n, u3n)));
        if ((t & 7) == 4) {
            if (lane == 0) red[wid] = lm;   // sampled max (16 rows/block)
            lm = 0.0f;
        }
        // rotate emission pipeline
        peA[0] = peB[0]; peA[1] = peB[1]; peA[2] = peB[2]; peA[3] = peB[3];
        peB[0] = __expf(rC[0]); peB[1] = __expf(rC[1]);
        peB[2] = __expf(rC[2]); peB[3] = __expf(rC[3]);
        rC[0] = rD[0]; rC[1] = rD[1]; rC[2] = rD[2]; rC[3] = rD[3];
        int tt = t + 4; tt = tt > last ? last : tt;
        const float* Ep = Ew + (size_t)tt * Nn;
        rD[0] = Ep[0]; rD[1] = Ep[8]; rD[2] = Ep[16]; rD[3] = Ep[24];
    };

    int t = 1;
    for (; t + 1 <= last; t += 2) {
        step(t, 0, 1);
        step(t + 1, 1, 0);
    }
    if (t <= last) step(t, 0, 1);

    __syncthreads();

    // out[b] = log( sum_j u_last[j] * exp(end[j]) ) + C
    float u  = __bfloat162float(ubuf[last & 1][permb(j)]);
    float ex = u * pend;
#pragma unroll
    for (int off = 16; off > 0; off >>= 1)
        ex += __shfl_xor_sync(0xffffffffu, ex, off);
    if (lane == 0) red[4 + wid] = ex;
    __syncthreads();
    if (j == 0)
        out[b] = __logf(red[4] + red[5] + red[6] + red[7]) + C;
}

extern "C" void kernel_launch(void* const* d_in, const int* in_sizes, int n_in,
                              void* d_out, int out_size) {
    const float* emissions   = (const float*)d_in[0];
    const float* transitions = (const float*)d_in[1];
    const float* start_t     = (const float*)d_in[2];
    const float* end_t       = (const float*)d_in[3];
    const int*   lengths     = (const int*)  d_in[4];
    crf_forward_kernel<<<Bb, Nn>>>(emissions, transitions, start_t, end_t,
                                   lengths, (float*)d_out);
}